// round 12
// baseline (speedup 1.0000x reference)
#include <cuda_runtime.h>
#include <cuda_bf16.h>
#include <stdint.h>
#include <math.h>

#define NND   50000
#define NPAD  50048              // 391*128
#define EE    800000
#define ET    (EE + NND)
#define GG    512
#define FIN   128
#define HID   128
#define HEADS 4
#define D1    512

// ---------------- scratch ----------------
// h1/h2 stored packed bf16x2 (hi precision only) for gather-side traffic
__device__ __align__(128) uint32_t g_h1p[(size_t)NPAD * (D1 / 2)];
__device__ __align__(128) uint32_t g_h2p[(size_t)NPAD * (HID / 2)];
// GEMM inputs: bf16 hi/lo packed (2 k-elements per u32 word)
__device__ __align__(128) uint32_t g_xh[(size_t)NPAD * (FIN / 2)];
__device__ __align__(128) uint32_t g_xl[(size_t)NPAD * (FIN / 2)];
__device__ __align__(128) uint32_t g_o1h[(size_t)NPAD * (D1 / 2)];
__device__ __align__(128) uint32_t g_o1l[(size_t)NPAD * (D1 / 2)];
__device__ __align__(128) uint32_t g_w1h[(FIN / 2) * D1];
__device__ __align__(128) uint32_t g_w1l[(FIN / 2) * D1];
__device__ __align__(128) uint32_t g_w2h[(D1 / 2) * HID];
__device__ __align__(128) uint32_t g_w2l[(D1 / 2) * HID];
__device__ __align__(128) float    g_as1[NND * HEADS];
__device__ __align__(128) float    g_ad1[NND * HEADS];
__device__ __align__(128) float    g_as2[NND];
__device__ __align__(128) float    g_ad2[NND];
__device__ __align__(128) float    g_pool[GG * HID];
__device__ __align__(128) float    g_cnt[GG];
// CSR
__device__ __align__(128) int g_deg[NND];
__device__ __align__(128) int g_rowptr[NND + 1];
__device__ __align__(128) int g_cursor[NND];
__device__ __align__(128) int g_colsrc[ET];
__device__ __align__(128) int g_bsum[128];

// ---------------- helpers ----------------
__device__ __forceinline__ float lrelu(float x) { return x > 0.f ? x : 0.2f * x; }
__device__ __forceinline__ float elu(float x)   { return x > 0.f ? x : __expf(x) - 1.f; }
__device__ __forceinline__ float wsum(float v) {
#pragma unroll
    for (int o = 16; o > 0; o >>= 1) v += __shfl_xor_sync(0xffffffffu, v, o);
    return v;
}
__device__ __forceinline__ float wmax(float v) {
#pragma unroll
    for (int o = 16; o > 0; o >>= 1) v = fmaxf(v, __shfl_xor_sync(0xffffffffu, v, o));
    return v;
}
__device__ __forceinline__ uint32_t packbf2(float a, float b) {
    __nv_bfloat162 p = __floats2bfloat162_rn(a, b);
    return *reinterpret_cast<uint32_t*>(&p);
}
__device__ __forceinline__ float2 unpackbf2(uint32_t u) {
    __nv_bfloat162 p = *reinterpret_cast<__nv_bfloat162*>(&u);
    return __bfloat1622float2(p);
}
// pack two floats into (hi bf16x2, lo bf16x2)
__device__ __forceinline__ uint2 packpair(float a, float b) {
    __nv_bfloat16 ha = __float2bfloat16(a), hb = __float2bfloat16(b);
    float ra = a - __bfloat162float(ha), rb = b - __bfloat162float(hb);
    __nv_bfloat16 la = __float2bfloat16(ra), lb = __float2bfloat16(rb);
    uint32_t hi = (uint32_t)__bfloat16_as_ushort(ha) |
                  ((uint32_t)__bfloat16_as_ushort(hb) << 16);
    uint32_t lo = (uint32_t)__bfloat16_as_ushort(la) |
                  ((uint32_t)__bfloat16_as_ushort(lb) << 16);
    return make_uint2(hi, lo);
}
__device__ __forceinline__ void mma_bf16(float4& d, const uint32_t* a, const uint32_t* b) {
    asm volatile(
        "mma.sync.aligned.m16n8k16.row.col.f32.bf16.bf16.f32 "
        "{%0,%1,%2,%3}, {%4,%5,%6,%7}, {%8,%9}, {%0,%1,%2,%3};"
        : "+f"(d.x), "+f"(d.y), "+f"(d.z), "+f"(d.w)
        : "r"(a[0]), "r"(a[1]), "r"(a[2]), "r"(a[3]), "r"(b[0]), "r"(b[1]));
}
__device__ __forceinline__ uint32_t smaddr(const void* p) {
    return (uint32_t)__cvta_generic_to_shared(p);
}
__device__ __forceinline__ void cpasync16(uint32_t dst, const void* src) {
    asm volatile("cp.async.cg.shared.global [%0], [%1], 16;" :: "r"(dst), "l"(src) : "memory");
}

// ---------------- zero / split ----------------
__global__ void zero_misc() {
    int i = blockIdx.x * blockDim.x + threadIdx.x;
    if (i < NND) g_deg[i] = 0;
    if (i < GG * HID) g_pool[i] = 0.f;
    if (i < GG) g_cnt[i] = 0.f;
}
__global__ void split_x(const float* __restrict__ x) {
    int i = blockIdx.x * blockDim.x + threadIdx.x;
    if (i >= NND * (FIN / 2)) return;
    int row = i >> 6, c = i & 63;
    uint2 p = packpair(x[row * FIN + 2 * c], x[row * FIN + 2 * c + 1]);
    g_xh[i] = p.x; g_xl[i] = p.y;
}
__global__ void split_w(const float* __restrict__ W1, const float* __restrict__ W2) {
    int i = blockIdx.x * blockDim.x + threadIdx.x;
    if (i < (FIN / 2) * D1) {
        int k2 = i / D1, n = i % D1;
        uint2 p = packpair(W1[(2 * k2) * D1 + n], W1[(2 * k2 + 1) * D1 + n]);
        g_w1h[i] = p.x; g_w1l[i] = p.y;
    }
    if (i < (D1 / 2) * HID) {
        int k2 = i / HID, n = i % HID;
        uint2 p = packpair(W2[(2 * k2) * HID + n], W2[(2 * k2 + 1) * HID + n]);
        g_w2h[i] = p.x; g_w2l[i] = p.y;
    }
}

// ---------------- CSR build ----------------
__global__ void deg_kernel(const int* __restrict__ dst) {
    int e = blockIdx.x * blockDim.x + threadIdx.x;
    if (e >= ET) return;
    int d = e < EE ? dst[e] : e - EE;
    atomicAdd(&g_deg[d], 1);
}
__global__ void scanA() {
    __shared__ int sm[512];
    int i = blockIdx.x * 512 + threadIdx.x;
    sm[threadIdx.x] = (i < NND) ? g_deg[i] : 0;
    __syncthreads();
#pragma unroll
    for (int o = 1; o < 512; o <<= 1) {
        int t = (threadIdx.x >= o) ? sm[threadIdx.x - o] : 0;
        __syncthreads();
        sm[threadIdx.x] += t;
        __syncthreads();
    }
    if (i < NND) g_rowptr[i + 1] = sm[threadIdx.x];
    if (threadIdx.x == 511) g_bsum[blockIdx.x] = sm[511];
}
__global__ void scanB(int nblk) {
    if (threadIdx.x == 0) {
        int run = 0;
        for (int b = 0; b < nblk; b++) { int t = g_bsum[b]; g_bsum[b] = run; run += t; }
        g_rowptr[0] = 0;
    }
}
__global__ void scanC() {
    int i = blockIdx.x * 512 + threadIdx.x;
    if (i < NND) {
        int v = g_rowptr[i + 1] + g_bsum[blockIdx.x];
        g_rowptr[i + 1] = v;
        g_cursor[i] = v - g_deg[i];
    }
}
__global__ void scatter_kernel(const int* __restrict__ src, const int* __restrict__ dst) {
    int e = blockIdx.x * blockDim.x + threadIdx.x;
    if (e >= ET) return;
    int s = e < EE ? src[e] : e - EE;
    int d = e < EE ? dst[e] : e - EE;
    int pos = atomicAdd(&g_cursor[d], 1);
    g_colsrc[pos] = s;
}

// ------------- bf16-split tensor GEMM, packed-bf16 output ---------------------
// C (packed bf16x2 words, N/2 per row) = A[NPAD,K] @ B[K,N]
#define A_STRIDE 12
#define B_STRIDE 136
#define A_BUF (128 * A_STRIDE)
#define B_BUF (8 * B_STRIDE)
#define GEMM_SMEM ((2 * A_BUF * 2 + 2 * B_BUF * 2) * (int)sizeof(uint32_t))
__global__ __launch_bounds__(256, 2) void tmma_gemm_b(const uint32_t* __restrict__ Ah,
                                                      const uint32_t* __restrict__ Al,
                                                      const uint32_t* __restrict__ Bh,
                                                      const uint32_t* __restrict__ Bl,
                                                      uint32_t* __restrict__ Cp,
                                                      int N, int K2) {
    extern __shared__ uint32_t smw[];
    uint32_t* sAH = smw;
    uint32_t* sAL = smw + 2 * A_BUF;
    uint32_t* sBH = smw + 4 * A_BUF;
    uint32_t* sBL = smw + 4 * A_BUF + 2 * B_BUF;
    int tid = threadIdx.x;
    int warp = tid >> 5, lane = tid & 31;
    int wm = warp & 3, wn = warp >> 2;
    int q = lane >> 2, r = lane & 3;
    int row0 = blockIdx.y * 128, col0 = blockIdx.x * 128;

    float4 acc[2][8];
#pragma unroll
    for (int i = 0; i < 2; i++)
#pragma unroll
        for (int j = 0; j < 8; j++) acc[i][j] = make_float4(0.f, 0.f, 0.f, 0.f);

    int ar = tid >> 1, ac = (tid & 1) * 4;
    int br = tid >> 5, bc = (tid & 31) * 4;

#define LOAD_TILE(buf, k2_0)                                                       \
    {                                                                              \
        cpasync16(smaddr(&sAH[(buf) * A_BUF + ar * A_STRIDE + ac]),                \
                  Ah + (size_t)(row0 + ar) * K2 + (k2_0) + ac);                    \
        cpasync16(smaddr(&sAL[(buf) * A_BUF + ar * A_STRIDE + ac]),                \
                  Al + (size_t)(row0 + ar) * K2 + (k2_0) + ac);                    \
        cpasync16(smaddr(&sBH[(buf) * B_BUF + br * B_STRIDE + bc]),                \
                  Bh + (size_t)((k2_0) + br) * N + col0 + bc);                     \
        cpasync16(smaddr(&sBL[(buf) * B_BUF + br * B_STRIDE + bc]),                \
                  Bl + (size_t)((k2_0) + br) * N + col0 + bc);                     \
        asm volatile("cp.async.commit_group;" ::: "memory");                       \
    }

    int nt = K2 >> 3;
    LOAD_TILE(0, 0);
    asm volatile("cp.async.wait_group 0;" ::: "memory");
    __syncthreads();

    for (int t = 0; t < nt; t++) {
        int buf = t & 1;
        if (t + 1 < nt) LOAD_TILE(buf ^ 1, (t + 1) * 8);

        uint32_t ah[2][4], al[2][4];
#pragma unroll
        for (int fm = 0; fm < 2; fm++) {
            int base = buf * A_BUF + (wm * 32 + fm * 16 + q) * A_STRIDE;
            ah[fm][0] = sAH[base + r];
            ah[fm][1] = sAH[base + 8 * A_STRIDE + r];
            ah[fm][2] = sAH[base + r + 4];
            ah[fm][3] = sAH[base + 8 * A_STRIDE + r + 4];
            al[fm][0] = sAL[base + r];
            al[fm][1] = sAL[base + 8 * A_STRIDE + r];
            al[fm][2] = sAL[base + r + 4];
            al[fm][3] = sAL[base + 8 * A_STRIDE + r + 4];
        }
#pragma unroll
        for (int fn = 0; fn < 8; fn++) {
            int ncol = wn * 64 + fn * 8 + q;
            uint32_t bh[2], bl[2];
            bh[0] = sBH[buf * B_BUF + r * B_STRIDE + ncol];
            bh[1] = sBH[buf * B_BUF + (r + 4) * B_STRIDE + ncol];
            bl[0] = sBL[buf * B_BUF + r * B_STRIDE + ncol];
            bl[1] = sBL[buf * B_BUF + (r + 4) * B_STRIDE + ncol];
#pragma unroll
            for (int fm = 0; fm < 2; fm++) {
                mma_bf16(acc[fm][fn], ah[fm], bh);
                mma_bf16(acc[fm][fn], ah[fm], bl);
                mma_bf16(acc[fm][fn], al[fm], bh);
            }
        }
        if (t + 1 < nt) asm volatile("cp.async.wait_group 0;" ::: "memory");
        __syncthreads();
    }

    int N2 = N >> 1;
#pragma unroll
    for (int fm = 0; fm < 2; fm++) {
        int r0 = row0 + wm * 32 + fm * 16 + q;
#pragma unroll
        for (int fn = 0; fn < 8; fn++) {
            int widx = ((col0 + wn * 64 + fn * 8) >> 1) + r;
            Cp[(size_t)r0 * N2 + widx]       = packbf2(acc[fm][fn].x, acc[fm][fn].y);
            Cp[(size_t)(r0 + 8) * N2 + widx] = packbf2(acc[fm][fn].z, acc[fm][fn].w);
        }
    }
#undef LOAD_TILE
}

// ---------------- attention scores (read packed bf16 h) ----------------
__global__ void scores1(const float* __restrict__ a_src, const float* __restrict__ a_dst) {
    int n = blockIdx.x;
    int w = threadIdx.x >> 5, l = threadIdx.x & 31;
    uint2 hw = *(const uint2*)(g_h1p + (size_t)n * (D1 / 2) + w * 64 + 2 * l);
    float2 h01 = unpackbf2(hw.x), h23 = unpackbf2(hw.y);
    float4 a = ((const float4*)(a_src + w * HID))[l];
    float4 d = ((const float4*)(a_dst + w * HID))[l];
    float s = h01.x * a.x + h01.y * a.y + h23.x * a.z + h23.y * a.w;
    float t = h01.x * d.x + h01.y * d.y + h23.x * d.z + h23.y * d.w;
    s = wsum(s); t = wsum(t);
    if (l == 0) { g_as1[n * HEADS + w] = s; g_ad1[n * HEADS + w] = t; }
}
__global__ void scores2(const float* __restrict__ a_src, const float* __restrict__ a_dst) {
    int gw = (blockIdx.x * blockDim.x + threadIdx.x) >> 5;
    int l = threadIdx.x & 31;
    if (gw >= NND) return;
    uint2 hw = *(const uint2*)(g_h2p + (size_t)gw * (HID / 2) + 2 * l);
    float2 h01 = unpackbf2(hw.x), h23 = unpackbf2(hw.y);
    float4 a = ((const float4*)a_src)[l];
    float4 d = ((const float4*)a_dst)[l];
    float s = h01.x * a.x + h01.y * a.y + h23.x * a.z + h23.y * a.w;
    float t = h01.x * d.x + h01.y * d.y + h23.x * d.z + h23.y * d.w;
    s = wsum(s); t = wsum(t);
    if (l == 0) { g_as2[gw] = s; g_ad2[gw] = t; }
}

// ---------------- fused layer-1 aggregation (block per dst node) -------------
__global__ __launch_bounds__(128) void gat_agg1(const float* __restrict__ b1) {
    int d = blockIdx.x;
    int t = threadIdx.x, w = t >> 5, l = t & 31;
    int beg = g_rowptr[d], end = g_rowptr[d + 1];
    float4 adv = ((const float4*)g_ad1)[d];

    __shared__ float4 s_red[4];
    __shared__ float4 s_bc[2];

    float4 pm = make_float4(-1e30f, -1e30f, -1e30f, -1e30f);
    for (int i = beg + t; i < end; i += 128) {
        float4 a = ((const float4*)g_as1)[g_colsrc[i]];
        pm.x = fmaxf(pm.x, lrelu(a.x + adv.x));
        pm.y = fmaxf(pm.y, lrelu(a.y + adv.y));
        pm.z = fmaxf(pm.z, lrelu(a.z + adv.z));
        pm.w = fmaxf(pm.w, lrelu(a.w + adv.w));
    }
    pm.x = wmax(pm.x); pm.y = wmax(pm.y); pm.z = wmax(pm.z); pm.w = wmax(pm.w);
    if (l == 0) s_red[w] = pm;
    __syncthreads();
    if (t == 0) {
        float4 m = s_red[0];
#pragma unroll
        for (int k = 1; k < 4; k++) {
            float4 r = s_red[k];
            m.x = fmaxf(m.x, r.x); m.y = fmaxf(m.y, r.y);
            m.z = fmaxf(m.z, r.z); m.w = fmaxf(m.w, r.w);
        }
        s_bc[0] = m;
    }
    __syncthreads();
    float4 mx = s_bc[0];

    float4 pd = make_float4(0.f, 0.f, 0.f, 0.f);
    for (int i = beg + t; i < end; i += 128) {
        float4 a = ((const float4*)g_as1)[g_colsrc[i]];
        pd.x += __expf(lrelu(a.x + adv.x) - mx.x);
        pd.y += __expf(lrelu(a.y + adv.y) - mx.y);
        pd.z += __expf(lrelu(a.z + adv.z) - mx.z);
        pd.w += __expf(lrelu(a.w + adv.w) - mx.w);
    }
    pd.x = wsum(pd.x); pd.y = wsum(pd.y); pd.z = wsum(pd.z); pd.w = wsum(pd.w);
    if (l == 0) s_red[w] = pd;
    __syncthreads();
    if (t == 0) {
        float4 s = s_red[0];
#pragma unroll
        for (int k = 1; k < 4; k++) {
            float4 r = s_red[k];
            s.x += r.x; s.y += r.y; s.z += r.z; s.w += r.w;
        }
        s_bc[1] = make_float4(1.f / s.x, 1.f / s.y, 1.f / s.z, 1.f / s.w);
    }
    __syncthreads();
    float4 inv = s_bc[1];
    float mxh  = (w == 0) ? mx.x  : (w == 1) ? mx.y  : (w == 2) ? mx.z  : mx.w;
    float invh = (w == 0) ? inv.x : (w == 1) ? inv.y : (w == 2) ? inv.z : inv.w;
    float advh = (w == 0) ? adv.x : (w == 1) ? adv.y : (w == 2) ? adv.z : adv.w;

    // pass 3: packed-bf16 gather (8 B per 4 values)
    float4 acc = make_float4(0.f, 0.f, 0.f, 0.f);
    for (int i = beg; i < end; i++) {
        int s = g_colsrc[i];
        float al = __expf(lrelu(g_as1[s * 4 + w] + advh) - mxh) * invh;
        uint2 hw = *(const uint2*)(g_h1p + (size_t)s * (D1 / 2) + 2 * t);
        float2 v01 = unpackbf2(hw.x), v23 = unpackbf2(hw.y);
        acc.x += al * v01.x; acc.y += al * v01.y;
        acc.z += al * v23.x; acc.w += al * v23.y;
    }
    float4 b = ((const float4*)b1)[t];
    acc.x = elu(acc.x + b.x); acc.y = elu(acc.y + b.y);
    acc.z = elu(acc.z + b.z); acc.w = elu(acc.w + b.w);
    uint2 p0 = packpair(acc.x, acc.y);
    uint2 p1 = packpair(acc.z, acc.w);
    *(uint2*)&g_o1h[(size_t)d * (D1 / 2) + 2 * t] = make_uint2(p0.x, p1.x);
    *(uint2*)&g_o1l[(size_t)d * (D1 / 2) + 2 * t] = make_uint2(p0.y, p1.y);
}

// ---------------- fused layer-2 aggregation + pool (warp per dst node) -------
__global__ __launch_bounds__(128) void gat_agg2(const float* __restrict__ b2,
                                                const int* __restrict__ batch) {
    int gw = (blockIdx.x * blockDim.x + threadIdx.x) >> 5;
    int l = threadIdx.x & 31;
    if (gw >= NND) return;
    int d = gw;
    int beg = g_rowptr[d], end = g_rowptr[d + 1];
    float adv = g_ad2[d];

    float mx = -1e30f;
    for (int i = beg + l; i < end; i += 32)
        mx = fmaxf(mx, lrelu(g_as2[g_colsrc[i]] + adv));
    mx = wmax(mx);

    float den = 0.f;
    for (int i = beg + l; i < end; i += 32)
        den += __expf(lrelu(g_as2[g_colsrc[i]] + adv) - mx);
    den = wsum(den);
    float inv = 1.f / den;

    float4 acc = make_float4(0.f, 0.f, 0.f, 0.f);
    for (int i = beg; i < end; i++) {
        int s = g_colsrc[i];
        float al = __expf(lrelu(g_as2[s] + adv) - mx) * inv;
        uint2 hw = *(const uint2*)(g_h2p + (size_t)s * (HID / 2) + 2 * l);
        float2 v01 = unpackbf2(hw.x), v23 = unpackbf2(hw.y);
        acc.x += al * v01.x; acc.y += al * v01.y;
        acc.z += al * v23.x; acc.w += al * v23.y;
    }
    float4 b = ((const float4*)b2)[l];
    acc.x = elu(acc.x + b.x); acc.y = elu(acc.y + b.y);
    acc.z = elu(acc.z + b.z); acc.w = elu(acc.w + b.w);
    int g = batch[d];
    atomicAdd((float4*)(g_pool + g * HID) + l, acc);
}

// ---------------- counts + final ----------------
__global__ void cnt_kernel(const int* __restrict__ batch) {
    int n = blockIdx.x * blockDim.x + threadIdx.x;
    if (n < NND) atomicAdd(&g_cnt[batch[n]], 1.0f);
}
__global__ void final_kernel(const float* __restrict__ Wl, const float* __restrict__ bl,
                             float* __restrict__ out) {
    int gw = (blockIdx.x * blockDim.x + threadIdx.x) >> 5;
    int l = threadIdx.x & 31;
    if (gw >= GG) return;
    float4 p = ((const float4*)g_pool)[gw * 32 + l];
    float4 w = ((const float4*)Wl)[l];
    float s = p.x * w.x + p.y * w.y + p.z * w.z + p.w * w.w;
    s = wsum(s);
    if (l == 0) out[gw] = s / fmaxf(g_cnt[gw], 1.0f) + bl[0];
}

// ---------------- launch ----------------
extern "C" void kernel_launch(void* const* d_in, const int* in_sizes, int n_in,
                              void* d_out, int out_size) {
    const float* x   = (const float*)d_in[0];
    const int*   ei  = (const int*)d_in[1];
    const int*   bat = (const int*)d_in[2];
    const float* W1  = (const float*)d_in[3];
    const float* as1 = (const float*)d_in[4];
    const float* ad1 = (const float*)d_in[5];
    const float* b1  = (const float*)d_in[6];
    const float* W2  = (const float*)d_in[7];
    const float* as2 = (const float*)d_in[8];
    const float* ad2 = (const float*)d_in[9];
    const float* b2  = (const float*)d_in[10];
    const float* Wl  = (const float*)d_in[11];
    const float* bl  = (const float*)d_in[12];
    float* out = (float*)d_out;
    const int* src = ei;
    const int* dst = ei + EE;

    uint32_t *p_xh, *p_xl, *p_o1h, *p_o1l, *p_w1h, *p_w1l, *p_w2h, *p_w2l;
    uint32_t *p_h1p, *p_h2p;
    cudaGetSymbolAddress((void**)&p_xh, g_xh);
    cudaGetSymbolAddress((void**)&p_xl, g_xl);
    cudaGetSymbolAddress((void**)&p_o1h, g_o1h);
    cudaGetSymbolAddress((void**)&p_o1l, g_o1l);
    cudaGetSymbolAddress((void**)&p_w1h, g_w1h);
    cudaGetSymbolAddress((void**)&p_w1l, g_w1l);
    cudaGetSymbolAddress((void**)&p_w2h, g_w2h);
    cudaGetSymbolAddress((void**)&p_w2l, g_w2l);
    cudaGetSymbolAddress((void**)&p_h1p, g_h1p);
    cudaGetSymbolAddress((void**)&p_h2p, g_h2p);

    cudaFuncSetAttribute(tmma_gemm_b, cudaFuncAttributeMaxDynamicSharedMemorySize,
                         GEMM_SMEM);

    int eb = (ET + 255) / 256;
    int nscan = (NND + 511) / 512;

    zero_misc<<<(GG * HID + 255) / 256 > (NND + 255) / 256 ? (GG * HID + 255) / 256
                                                           : (NND + 255) / 256, 256>>>();
    split_x<<<(NND * (FIN / 2) + 255) / 256, 256>>>(x);
    split_w<<<((D1 / 2) * HID + 255) / 256 > ((FIN / 2) * D1 + 255) / 256
                  ? ((D1 / 2) * HID + 255) / 256
                  : ((FIN / 2) * D1 + 255) / 256, 256>>>(W1, W2);
    // GEMM1 at launch index 3 (ncu profiles this one)
    tmma_gemm_b<<<dim3(D1 / 128, NPAD / 128), 256, GEMM_SMEM>>>(
        p_xh, p_xl, p_w1h, p_w1l, p_h1p, D1, FIN / 2);
    // CSR build
    deg_kernel<<<eb, 256>>>(dst);
    scanA<<<nscan, 512>>>();
    scanB<<<1, 32>>>(nscan);
    scanC<<<nscan, 512>>>();
    scatter_kernel<<<eb, 256>>>(src, dst);

    // Layer 1
    scores1<<<NND, 128>>>(as1, ad1);
    gat_agg1<<<NND, 128>>>(b1);

    // Layer 2
    tmma_gemm_b<<<dim3(HID / 128, NPAD / 128), 256, GEMM_SMEM>>>(
        p_o1h, p_o1l, p_w2h, p_w2l, p_h2p, HID, D1 / 2);
    scores2<<<(NND * 32 + 127) / 128, 128>>>(as2, ad2);
    gat_agg2<<<(NND * 32 + 127) / 128, 128>>>(b2, bat);

    cnt_kernel<<<(NND + 255) / 256, 256>>>(bat);
    final_kernel<<<(GG * 32 + 255) / 256, 256>>>(Wl, bl, out);
}

// round 13
// speedup vs baseline: 1.0653x; 1.0653x over previous
#include <cuda_runtime.h>
#include <cuda_bf16.h>
#include <stdint.h>
#include <math.h>

#define NND   50000
#define NPAD  50048              // 391*128
#define EE    800000
#define ET    (EE + NND)
#define GG    512
#define FIN   128
#define HID   128
#define HEADS 4
#define D1    512

// ---------------- scratch ----------------
__device__ __align__(128) float    g_h1[(size_t)NPAD * D1];
__device__ __align__(128) float    g_h2[(size_t)NPAD * HID];
// GEMM inputs: bf16 hi/lo packed (2 k-elements per u32 word)
__device__ __align__(128) uint32_t g_xh[(size_t)NPAD * (FIN / 2)];
__device__ __align__(128) uint32_t g_xl[(size_t)NPAD * (FIN / 2)];
__device__ __align__(128) uint32_t g_o1h[(size_t)NPAD * (D1 / 2)];
__device__ __align__(128) uint32_t g_o1l[(size_t)NPAD * (D1 / 2)];
__device__ __align__(128) uint32_t g_w1h[(FIN / 2) * D1];
__device__ __align__(128) uint32_t g_w1l[(FIN / 2) * D1];
__device__ __align__(128) uint32_t g_w2h[(D1 / 2) * HID];
__device__ __align__(128) uint32_t g_w2l[(D1 / 2) * HID];
__device__ __align__(128) float    g_as1[NND * HEADS];
__device__ __align__(128) float    g_ad1[NND * HEADS];
__device__ __align__(128) float    g_as2[NND];
__device__ __align__(128) float    g_ad2[NND];
__device__ __align__(128) float    g_pool[GG * HID];
__device__ __align__(128) float    g_cnt[GG];
// CSR
__device__ __align__(128) int g_deg[NND];
__device__ __align__(128) int g_rowptr[NND + 1];
__device__ __align__(128) int g_cursor[NND];
__device__ __align__(128) int g_colsrc[ET];
__device__ __align__(128) int g_bsum[128];

// ---------------- helpers ----------------
__device__ __forceinline__ float lrelu(float x) { return x > 0.f ? x : 0.2f * x; }
__device__ __forceinline__ float elu(float x)   { return x > 0.f ? x : __expf(x) - 1.f; }
__device__ __forceinline__ float wsum(float v) {
#pragma unroll
    for (int o = 16; o > 0; o >>= 1) v += __shfl_xor_sync(0xffffffffu, v, o);
    return v;
}
__device__ __forceinline__ float wmax(float v) {
#pragma unroll
    for (int o = 16; o > 0; o >>= 1) v = fmaxf(v, __shfl_xor_sync(0xffffffffu, v, o));
    return v;
}
// pack two floats into (hi bf16x2, lo bf16x2)
__device__ __forceinline__ uint2 packpair(float a, float b) {
    __nv_bfloat16 ha = __float2bfloat16(a), hb = __float2bfloat16(b);
    float ra = a - __bfloat162float(ha), rb = b - __bfloat162float(hb);
    __nv_bfloat16 la = __float2bfloat16(ra), lb = __float2bfloat16(rb);
    uint32_t hi = (uint32_t)__bfloat16_as_ushort(ha) |
                  ((uint32_t)__bfloat16_as_ushort(hb) << 16);
    uint32_t lo = (uint32_t)__bfloat16_as_ushort(la) |
                  ((uint32_t)__bfloat16_as_ushort(lb) << 16);
    return make_uint2(hi, lo);
}
__device__ __forceinline__ void mma_bf16(float4& d, const uint32_t* a, const uint32_t* b) {
    asm volatile(
        "mma.sync.aligned.m16n8k16.row.col.f32.bf16.bf16.f32 "
        "{%0,%1,%2,%3}, {%4,%5,%6,%7}, {%8,%9}, {%0,%1,%2,%3};"
        : "+f"(d.x), "+f"(d.y), "+f"(d.z), "+f"(d.w)
        : "r"(a[0]), "r"(a[1]), "r"(a[2]), "r"(a[3]), "r"(b[0]), "r"(b[1]));
}
__device__ __forceinline__ uint32_t smaddr(const void* p) {
    return (uint32_t)__cvta_generic_to_shared(p);
}
__device__ __forceinline__ void cpasync16(uint32_t dst, const void* src) {
    asm volatile("cp.async.cg.shared.global [%0], [%1], 16;" :: "r"(dst), "l"(src) : "memory");
}

// ---------------- zero / split ----------------
__global__ void zero_misc() {
    int i = blockIdx.x * blockDim.x + threadIdx.x;
    if (i < NND) g_deg[i] = 0;
    if (i < GG * HID) g_pool[i] = 0.f;
    if (i < GG) g_cnt[i] = 0.f;
}
__global__ void split_x(const float* __restrict__ x) {
    int i = blockIdx.x * blockDim.x + threadIdx.x;
    if (i >= NND * (FIN / 2)) return;
    int row = i >> 6, c = i & 63;
    uint2 p = packpair(x[row * FIN + 2 * c], x[row * FIN + 2 * c + 1]);
    g_xh[i] = p.x; g_xl[i] = p.y;
}
__global__ void split_w(const float* __restrict__ W1, const float* __restrict__ W2) {
    int i = blockIdx.x * blockDim.x + threadIdx.x;
    if (i < (FIN / 2) * D1) {
        int k2 = i / D1, n = i % D1;
        uint2 p = packpair(W1[(2 * k2) * D1 + n], W1[(2 * k2 + 1) * D1 + n]);
        g_w1h[i] = p.x; g_w1l[i] = p.y;
    }
    if (i < (D1 / 2) * HID) {
        int k2 = i / HID, n = i % HID;
        uint2 p = packpair(W2[(2 * k2) * HID + n], W2[(2 * k2 + 1) * HID + n]);
        g_w2h[i] = p.x; g_w2l[i] = p.y;
    }
}

// ---------------- CSR build ----------------
__global__ void deg_kernel(const int* __restrict__ dst) {
    int e = blockIdx.x * blockDim.x + threadIdx.x;
    if (e >= ET) return;
    int d = e < EE ? dst[e] : e - EE;
    atomicAdd(&g_deg[d], 1);
}
__global__ void scanA() {
    __shared__ int sm[512];
    int i = blockIdx.x * 512 + threadIdx.x;
    sm[threadIdx.x] = (i < NND) ? g_deg[i] : 0;
    __syncthreads();
#pragma unroll
    for (int o = 1; o < 512; o <<= 1) {
        int t = (threadIdx.x >= o) ? sm[threadIdx.x - o] : 0;
        __syncthreads();
        sm[threadIdx.x] += t;
        __syncthreads();
    }
    if (i < NND) g_rowptr[i + 1] = sm[threadIdx.x];
    if (threadIdx.x == 511) g_bsum[blockIdx.x] = sm[511];
}
__global__ void scanB(int nblk) {
    if (threadIdx.x == 0) {
        int run = 0;
        for (int b = 0; b < nblk; b++) { int t = g_bsum[b]; g_bsum[b] = run; run += t; }
        g_rowptr[0] = 0;
    }
}
__global__ void scanC() {
    int i = blockIdx.x * 512 + threadIdx.x;
    if (i < NND) {
        int v = g_rowptr[i + 1] + g_bsum[blockIdx.x];
        g_rowptr[i + 1] = v;
        g_cursor[i] = v - g_deg[i];
    }
}
__global__ void scatter_kernel(const int* __restrict__ src, const int* __restrict__ dst) {
    int e = blockIdx.x * blockDim.x + threadIdx.x;
    if (e >= ET) return;
    int s = e < EE ? src[e] : e - EE;
    int d = e < EE ? dst[e] : e - EE;
    int pos = atomicAdd(&g_cursor[d], 1);
    g_colsrc[pos] = s;
}

// ------------- bf16-split tensor GEMM: C[NPAD,N] (f32) = A @ B ---------------
#define A_STRIDE 12
#define B_STRIDE 136
#define A_BUF (128 * A_STRIDE)
#define B_BUF (8 * B_STRIDE)
#define GEMM_SMEM ((2 * A_BUF * 2 + 2 * B_BUF * 2) * (int)sizeof(uint32_t))
__global__ __launch_bounds__(256, 2) void tmma_gemm_b(const uint32_t* __restrict__ Ah,
                                                      const uint32_t* __restrict__ Al,
                                                      const uint32_t* __restrict__ Bh,
                                                      const uint32_t* __restrict__ Bl,
                                                      float* __restrict__ C,
                                                      int N, int K2) {
    extern __shared__ uint32_t smw[];
    uint32_t* sAH = smw;
    uint32_t* sAL = smw + 2 * A_BUF;
    uint32_t* sBH = smw + 4 * A_BUF;
    uint32_t* sBL = smw + 4 * A_BUF + 2 * B_BUF;
    int tid = threadIdx.x;
    int warp = tid >> 5, lane = tid & 31;
    int wm = warp & 3, wn = warp >> 2;
    int q = lane >> 2, r = lane & 3;
    int row0 = blockIdx.y * 128, col0 = blockIdx.x * 128;

    float4 acc[2][8];
#pragma unroll
    for (int i = 0; i < 2; i++)
#pragma unroll
        for (int j = 0; j < 8; j++) acc[i][j] = make_float4(0.f, 0.f, 0.f, 0.f);

    int ar = tid >> 1, ac = (tid & 1) * 4;
    int br = tid >> 5, bc = (tid & 31) * 4;

#define LOAD_TILE(buf, k2_0)                                                       \
    {                                                                              \
        cpasync16(smaddr(&sAH[(buf) * A_BUF + ar * A_STRIDE + ac]),                \
                  Ah + (size_t)(row0 + ar) * K2 + (k2_0) + ac);                    \
        cpasync16(smaddr(&sAL[(buf) * A_BUF + ar * A_STRIDE + ac]),                \
                  Al + (size_t)(row0 + ar) * K2 + (k2_0) + ac);                    \
        cpasync16(smaddr(&sBH[(buf) * B_BUF + br * B_STRIDE + bc]),                \
                  Bh + (size_t)((k2_0) + br) * N + col0 + bc);                     \
        cpasync16(smaddr(&sBL[(buf) * B_BUF + br * B_STRIDE + bc]),                \
                  Bl + (size_t)((k2_0) + br) * N + col0 + bc);                     \
        asm volatile("cp.async.commit_group;" ::: "memory");                       \
    }

    int nt = K2 >> 3;
    LOAD_TILE(0, 0);
    asm volatile("cp.async.wait_group 0;" ::: "memory");
    __syncthreads();

    for (int t = 0; t < nt; t++) {
        int buf = t & 1;
        if (t + 1 < nt) LOAD_TILE(buf ^ 1, (t + 1) * 8);

        uint32_t ah[2][4], al[2][4];
#pragma unroll
        for (int fm = 0; fm < 2; fm++) {
            int base = buf * A_BUF + (wm * 32 + fm * 16 + q) * A_STRIDE;
            ah[fm][0] = sAH[base + r];
            ah[fm][1] = sAH[base + 8 * A_STRIDE + r];
            ah[fm][2] = sAH[base + r + 4];
            ah[fm][3] = sAH[base + 8 * A_STRIDE + r + 4];
            al[fm][0] = sAL[base + r];
            al[fm][1] = sAL[base + 8 * A_STRIDE + r];
            al[fm][2] = sAL[base + r + 4];
            al[fm][3] = sAL[base + 8 * A_STRIDE + r + 4];
        }
#pragma unroll
        for (int fn = 0; fn < 8; fn++) {
            int ncol = wn * 64 + fn * 8 + q;
            uint32_t bh[2], bl[2];
            bh[0] = sBH[buf * B_BUF + r * B_STRIDE + ncol];
            bh[1] = sBH[buf * B_BUF + (r + 4) * B_STRIDE + ncol];
            bl[0] = sBL[buf * B_BUF + r * B_STRIDE + ncol];
            bl[1] = sBL[buf * B_BUF + (r + 4) * B_STRIDE + ncol];
#pragma unroll
            for (int fm = 0; fm < 2; fm++) {
                mma_bf16(acc[fm][fn], ah[fm], bh);
                mma_bf16(acc[fm][fn], ah[fm], bl);
                mma_bf16(acc[fm][fn], al[fm], bh);
            }
        }
        if (t + 1 < nt) asm volatile("cp.async.wait_group 0;" ::: "memory");
        __syncthreads();
    }

#pragma unroll
    for (int fm = 0; fm < 2; fm++) {
        int r0 = row0 + wm * 32 + fm * 16 + q;
#pragma unroll
        for (int fn = 0; fn < 8; fn++) {
            int cidx = col0 + wn * 64 + fn * 8 + r * 2;
            *(float2*)(C + (size_t)r0 * N + cidx) =
                make_float2(acc[fm][fn].x, acc[fm][fn].y);
            *(float2*)(C + (size_t)(r0 + 8) * N + cidx) =
                make_float2(acc[fm][fn].z, acc[fm][fn].w);
        }
    }
#undef LOAD_TILE
}

// ---------------- attention scores ----------------
__global__ void scores1(const float* __restrict__ a_src, const float* __restrict__ a_dst) {
    int n = blockIdx.x;
    int w = threadIdx.x >> 5, l = threadIdx.x & 31;
    float4 h = ((const float4*)(g_h1 + (size_t)n * D1 + w * HID))[l];
    float4 a = ((const float4*)(a_src + w * HID))[l];
    float4 d = ((const float4*)(a_dst + w * HID))[l];
    float s = h.x * a.x + h.y * a.y + h.z * a.z + h.w * a.w;
    float t = h.x * d.x + h.y * d.y + h.z * d.z + h.w * d.w;
    s = wsum(s); t = wsum(t);
    if (l == 0) { g_as1[n * HEADS + w] = s; g_ad1[n * HEADS + w] = t; }
}
__global__ void scores2(const float* __restrict__ a_src, const float* __restrict__ a_dst) {
    int gw = (blockIdx.x * blockDim.x + threadIdx.x) >> 5;
    int l = threadIdx.x & 31;
    if (gw >= NND) return;
    float4 h = ((const float4*)g_h2)[(size_t)gw * 32 + l];
    float4 a = ((const float4*)a_src)[l];
    float4 d = ((const float4*)a_dst)[l];
    float s = h.x * a.x + h.y * a.y + h.z * a.z + h.w * a.w;
    float t = h.x * d.x + h.y * d.y + h.z * d.z + h.w * d.w;
    s = wsum(s); t = wsum(t);
    if (l == 0) { g_as2[gw] = s; g_ad2[gw] = t; }
}

// ---------------- fused layer-1 aggregation (block per dst node) -------------
// Pass 3 uses lane-parallel alpha computation + shfl broadcast (issue-bound fix).
__global__ __launch_bounds__(128) void gat_agg1(const float* __restrict__ b1) {
    int d = blockIdx.x;
    int t = threadIdx.x, w = t >> 5, l = t & 31;
    int beg = g_rowptr[d], end = g_rowptr[d + 1];
    float4 adv = ((const float4*)g_ad1)[d];

    __shared__ float4 s_red[4];
    __shared__ float4 s_bc[2];

    float4 pm = make_float4(-1e30f, -1e30f, -1e30f, -1e30f);
    for (int i = beg + t; i < end; i += 128) {
        float4 a = ((const float4*)g_as1)[g_colsrc[i]];
        pm.x = fmaxf(pm.x, lrelu(a.x + adv.x));
        pm.y = fmaxf(pm.y, lrelu(a.y + adv.y));
        pm.z = fmaxf(pm.z, lrelu(a.z + adv.z));
        pm.w = fmaxf(pm.w, lrelu(a.w + adv.w));
    }
    pm.x = wmax(pm.x); pm.y = wmax(pm.y); pm.z = wmax(pm.z); pm.w = wmax(pm.w);
    if (l == 0) s_red[w] = pm;
    __syncthreads();
    if (t == 0) {
        float4 m = s_red[0];
#pragma unroll
        for (int k = 1; k < 4; k++) {
            float4 r = s_red[k];
            m.x = fmaxf(m.x, r.x); m.y = fmaxf(m.y, r.y);
            m.z = fmaxf(m.z, r.z); m.w = fmaxf(m.w, r.w);
        }
        s_bc[0] = m;
    }
    __syncthreads();
    float4 mx = s_bc[0];

    float4 pd = make_float4(0.f, 0.f, 0.f, 0.f);
    for (int i = beg + t; i < end; i += 128) {
        float4 a = ((const float4*)g_as1)[g_colsrc[i]];
        pd.x += __expf(lrelu(a.x + adv.x) - mx.x);
        pd.y += __expf(lrelu(a.y + adv.y) - mx.y);
        pd.z += __expf(lrelu(a.z + adv.z) - mx.z);
        pd.w += __expf(lrelu(a.w + adv.w) - mx.w);
    }
    pd.x = wsum(pd.x); pd.y = wsum(pd.y); pd.z = wsum(pd.z); pd.w = wsum(pd.w);
    if (l == 0) s_red[w] = pd;
    __syncthreads();
    if (t == 0) {
        float4 s = s_red[0];
#pragma unroll
        for (int k = 1; k < 4; k++) {
            float4 r = s_red[k];
            s.x += r.x; s.y += r.y; s.z += r.z; s.w += r.w;
        }
        s_bc[1] = make_float4(1.f / s.x, 1.f / s.y, 1.f / s.z, 1.f / s.w);
    }
    __syncthreads();
    float4 inv = s_bc[1];
    float mxh  = (w == 0) ? mx.x  : (w == 1) ? mx.y  : (w == 2) ? mx.z  : mx.w;
    float invh = (w == 0) ? inv.x : (w == 1) ? inv.y : (w == 2) ? inv.z : inv.w;
    float advh = (w == 0) ? adv.x : (w == 1) ? adv.y : (w == 2) ? adv.z : adv.w;

    // pass 3: chunk of 32 edges; lane j owns alpha_j; broadcast via shfl
    float4 acc = make_float4(0.f, 0.f, 0.f, 0.f);
    for (int base = beg; base < end; base += 32) {
        int i = base + l;
        float my_al = 0.f; int my_s = 0;
        if (i < end) {
            my_s = g_colsrc[i];
            my_al = __expf(lrelu(g_as1[my_s * 4 + w] + advh) - mxh) * invh;
        }
        int cnt = min(32, end - base);
        if (cnt == 32) {
#pragma unroll 8
            for (int j = 0; j < 32; j++) {
                float al = __shfl_sync(0xffffffffu, my_al, j);
                int s = __shfl_sync(0xffffffffu, my_s, j);
                float4 v = ((const float4*)(g_h1 + (size_t)s * D1))[t];
                acc.x += al * v.x; acc.y += al * v.y;
                acc.z += al * v.z; acc.w += al * v.w;
            }
        } else {
            for (int j = 0; j < cnt; j++) {
                float al = __shfl_sync(0xffffffffu, my_al, j);
                int s = __shfl_sync(0xffffffffu, my_s, j);
                float4 v = ((const float4*)(g_h1 + (size_t)s * D1))[t];
                acc.x += al * v.x; acc.y += al * v.y;
                acc.z += al * v.z; acc.w += al * v.w;
            }
        }
    }
    float4 b = ((const float4*)b1)[t];
    acc.x = elu(acc.x + b.x); acc.y = elu(acc.y + b.y);
    acc.z = elu(acc.z + b.z); acc.w = elu(acc.w + b.w);
    uint2 p0 = packpair(acc.x, acc.y);
    uint2 p1 = packpair(acc.z, acc.w);
    *(uint2*)&g_o1h[(size_t)d * (D1 / 2) + 2 * t] = make_uint2(p0.x, p1.x);
    *(uint2*)&g_o1l[(size_t)d * (D1 / 2) + 2 * t] = make_uint2(p0.y, p1.y);
}

// ---------------- fused layer-2 aggregation + pool (warp per dst node) -------
__global__ __launch_bounds__(128) void gat_agg2(const float* __restrict__ b2,
                                                const int* __restrict__ batch) {
    int gw = (blockIdx.x * blockDim.x + threadIdx.x) >> 5;
    int l = threadIdx.x & 31;
    if (gw >= NND) return;
    int d = gw;
    int beg = g_rowptr[d], end = g_rowptr[d + 1];
    float adv = g_ad2[d];

    float mx = -1e30f;
    for (int i = beg + l; i < end; i += 32)
        mx = fmaxf(mx, lrelu(g_as2[g_colsrc[i]] + adv));
    mx = wmax(mx);

    float den = 0.f;
    for (int i = beg + l; i < end; i += 32)
        den += __expf(lrelu(g_as2[g_colsrc[i]] + adv) - mx);
    den = wsum(den);
    float inv = 1.f / den;

    float4 acc = make_float4(0.f, 0.f, 0.f, 0.f);
    for (int base = beg; base < end; base += 32) {
        int i = base + l;
        float my_al = 0.f; int my_s = 0;
        if (i < end) {
            my_s = g_colsrc[i];
            my_al = __expf(lrelu(g_as2[my_s] + adv) - mx) * inv;
        }
        int cnt = min(32, end - base);
        if (cnt == 32) {
#pragma unroll 8
            for (int j = 0; j < 32; j++) {
                float al = __shfl_sync(0xffffffffu, my_al, j);
                int s = __shfl_sync(0xffffffffu, my_s, j);
                float4 v = ((const float4*)(g_h2 + (size_t)s * HID))[l];
                acc.x += al * v.x; acc.y += al * v.y;
                acc.z += al * v.z; acc.w += al * v.w;
            }
        } else {
            for (int j = 0; j < cnt; j++) {
                float al = __shfl_sync(0xffffffffu, my_al, j);
                int s = __shfl_sync(0xffffffffu, my_s, j);
                float4 v = ((const float4*)(g_h2 + (size_t)s * HID))[l];
                acc.x += al * v.x; acc.y += al * v.y;
                acc.z += al * v.z; acc.w += al * v.w;
            }
        }
    }
    float4 b = ((const float4*)b2)[l];
    acc.x = elu(acc.x + b.x); acc.y = elu(acc.y + b.y);
    acc.z = elu(acc.z + b.z); acc.w = elu(acc.w + b.w);
    int g = batch[d];
    atomicAdd((float4*)(g_pool + g * HID) + l, acc);
}

// ---------------- counts + final ----------------
__global__ void cnt_kernel(const int* __restrict__ batch) {
    int n = blockIdx.x * blockDim.x + threadIdx.x;
    if (n < NND) atomicAdd(&g_cnt[batch[n]], 1.0f);
}
__global__ void final_kernel(const float* __restrict__ Wl, const float* __restrict__ bl,
                             float* __restrict__ out) {
    int gw = (blockIdx.x * blockDim.x + threadIdx.x) >> 5;
    int l = threadIdx.x & 31;
    if (gw >= GG) return;
    float4 p = ((const float4*)g_pool)[gw * 32 + l];
    float4 w = ((const float4*)Wl)[l];
    float s = p.x * w.x + p.y * w.y + p.z * w.z + p.w * w.w;
    s = wsum(s);
    if (l == 0) out[gw] = s / fmaxf(g_cnt[gw], 1.0f) + bl[0];
}

// ---------------- launch ----------------
extern "C" void kernel_launch(void* const* d_in, const int* in_sizes, int n_in,
                              void* d_out, int out_size) {
    const float* x   = (const float*)d_in[0];
    const int*   ei  = (const int*)d_in[1];
    const int*   bat = (const int*)d_in[2];
    const float* W1  = (const float*)d_in[3];
    const float* as1 = (const float*)d_in[4];
    const float* ad1 = (const float*)d_in[5];
    const float* b1  = (const float*)d_in[6];
    const float* W2  = (const float*)d_in[7];
    const float* as2 = (const float*)d_in[8];
    const float* ad2 = (const float*)d_in[9];
    const float* b2  = (const float*)d_in[10];
    const float* Wl  = (const float*)d_in[11];
    const float* bl  = (const float*)d_in[12];
    float* out = (float*)d_out;
    const int* src = ei;
    const int* dst = ei + EE;

    uint32_t *p_xh, *p_xl, *p_o1h, *p_o1l, *p_w1h, *p_w1l, *p_w2h, *p_w2l;
    float *p_h1, *p_h2;
    cudaGetSymbolAddress((void**)&p_xh, g_xh);
    cudaGetSymbolAddress((void**)&p_xl, g_xl);
    cudaGetSymbolAddress((void**)&p_o1h, g_o1h);
    cudaGetSymbolAddress((void**)&p_o1l, g_o1l);
    cudaGetSymbolAddress((void**)&p_w1h, g_w1h);
    cudaGetSymbolAddress((void**)&p_w1l, g_w1l);
    cudaGetSymbolAddress((void**)&p_w2h, g_w2h);
    cudaGetSymbolAddress((void**)&p_w2l, g_w2l);
    cudaGetSymbolAddress((void**)&p_h1, g_h1);
    cudaGetSymbolAddress((void**)&p_h2, g_h2);

    cudaFuncSetAttribute(tmma_gemm_b, cudaFuncAttributeMaxDynamicSharedMemorySize,
                         GEMM_SMEM);

    int eb = (ET + 255) / 256;
    int nscan = (NND + 511) / 512;

    zero_misc<<<(GG * HID + 255) / 256 > (NND + 255) / 256 ? (GG * HID + 255) / 256
                                                           : (NND + 255) / 256, 256>>>();
    split_x<<<(NND * (FIN / 2) + 255) / 256, 256>>>(x);
    split_w<<<((D1 / 2) * HID + 255) / 256 > ((FIN / 2) * D1 + 255) / 256
                  ? ((D1 / 2) * HID + 255) / 256
                  : ((FIN / 2) * D1 + 255) / 256, 256>>>(W1, W2);
    // GEMM1 at launch index 3 (ncu profiles this one)
    tmma_gemm_b<<<dim3(D1 / 128, NPAD / 128), 256, GEMM_SMEM>>>(
        p_xh, p_xl, p_w1h, p_w1l, p_h1, D1, FIN / 2);
    // CSR build
    deg_kernel<<<eb, 256>>>(dst);
    scanA<<<nscan, 512>>>();
    scanB<<<1, 32>>>(nscan);
    scanC<<<nscan, 512>>>();
    scatter_kernel<<<eb, 256>>>(src, dst);

    // Layer 1
    scores1<<<NND, 128>>>(as1, ad1);
    gat_agg1<<<NND, 128>>>(b1);

    // Layer 2
    tmma_gemm_b<<<dim3(HID / 128, NPAD / 128), 256, GEMM_SMEM>>>(
        p_o1h, p_o1l, p_w2h, p_w2l, p_h2, HID, D1 / 2);
    scores2<<<(NND * 32 + 127) / 128, 128>>>(as2, ad2);
    gat_agg2<<<(NND * 32 + 127) / 128, 128>>>(b2, bat);

    cnt_kernel<<<(NND + 255) / 256, 256>>>(bat);
    final_kernel<<<(GG * 32 + 255) / 256, 256>>>(Wl, bl, out);
}